// round 7
// baseline (speedup 1.0000x reference)
#include <cuda_runtime.h>
#include <math.h>

#define SQ 2048   // sequence length
#define BB 64     // batch
#define DI 512    // input dim
#define HD 512    // hidden dim
#define G4 2048   // 4*HD

#define NBLK 128          // persistent blocks, 1/SM, co-resident
#define TPB 128           // threads per persistent block (4 warps)
#define HPAD 516          // padded h row (floats): conflict-free quarter-warp LDS.128
#define WPAD 516

// ---- device scratch (allocation-free per the rules) ----
__device__ float g_xproj[2048ULL * 64ULL * 2048ULL];  // 1 GiB: x @ W_ih^T
__device__ int   g_flag[NBLK];                        // per-block step flags (zero-init)
__device__ unsigned long long g_bar;                  // legacy ticket barrier (end-of-launch only)

// ---- packed f32x2 helpers ----
__device__ __forceinline__ void fma2(unsigned long long& d,
                                     unsigned long long a, unsigned long long b) {
    asm("fma.rn.f32x2 %0, %1, %2, %0;" : "+l"(d) : "l"(a), "l"(b));
}
__device__ __forceinline__ float red2(unsigned long long v) {
    float lo, hi;
    asm("mov.b64 {%0, %1}, %2;" : "=f"(lo), "=f"(hi) : "l"(v));
    return lo + hi;
}

__device__ __forceinline__ float sigf(float x) { return 1.0f / (1.0f + __expf(-x)); }

// Legacy grid barrier (used ONCE at kernel end, before flag reset).
__device__ __forceinline__ void gridbar(unsigned nb) {
    __threadfence();
    __syncthreads();
    if (threadIdx.x == 0) {
        unsigned long long t = atomicAdd(&g_bar, 1ULL) + 1ULL;
        unsigned long long target = ((t + nb - 1ULL) / nb) * (unsigned long long)nb;
        while (*((volatile unsigned long long*)&g_bar) < target) { }
        __threadfence();
    }
    __syncthreads();
}

// ============================================================================
// Kernel 1: x_proj[m][n] = sum_k x[m][k] * W_ih[n][k]     (plain fp32 SGEMM)
// M=131072, N=2048, K=512. 128x128 tile, BK=8, 256 thr, 8x8 microtile.
// ============================================================================
__global__ __launch_bounds__(256, 2)
void xproj_gemm(const float* __restrict__ A, const float* __restrict__ W)
{
    __shared__ float As[8][128];
    __shared__ float Bs[8][128];

    const int bn  = blockIdx.x;
    const int bm  = blockIdx.y;
    const int tid = threadIdx.x;

    const int arow = tid >> 1;
    const int acol = (tid & 1) << 2;
    const float* Ag = A + (size_t)(bm * 128 + arow) * DI + acol;
    const float* Wg = W + (size_t)(bn * 128 + arow) * DI + acol;

    const int tx = tid & 15;
    const int ty = tid >> 4;

    float acc[8][8];
#pragma unroll
    for (int i = 0; i < 8; i++)
#pragma unroll
        for (int j = 0; j < 8; j++) acc[i][j] = 0.0f;

    for (int kt = 0; kt < DI; kt += 8) {
        float4 av = *(const float4*)(Ag + kt);
        float4 wv = *(const float4*)(Wg + kt);
        __syncthreads();
        As[acol + 0][arow] = av.x; As[acol + 1][arow] = av.y;
        As[acol + 2][arow] = av.z; As[acol + 3][arow] = av.w;
        Bs[acol + 0][arow] = wv.x; Bs[acol + 1][arow] = wv.y;
        Bs[acol + 2][arow] = wv.z; Bs[acol + 3][arow] = wv.w;
        __syncthreads();
#pragma unroll
        for (int k = 0; k < 8; k++) {
            float ar[8], br[8];
            *(float4*)(ar)     = *(const float4*)&As[k][ty * 8];
            *(float4*)(ar + 4) = *(const float4*)&As[k][ty * 8 + 4];
            *(float4*)(br)     = *(const float4*)&Bs[k][tx * 8];
            *(float4*)(br + 4) = *(const float4*)&Bs[k][tx * 8 + 4];
#pragma unroll
            for (int i = 0; i < 8; i++)
#pragma unroll
                for (int j = 0; j < 8; j++)
                    acc[i][j] += ar[i] * br[j];
        }
    }

    float* Cp = g_xproj + (size_t)(bm * 128 + ty * 8) * G4 + (size_t)(bn * 128 + tx * 8);
#pragma unroll
    for (int i = 0; i < 8; i++) {
        *(float4*)(Cp + (size_t)i * G4)     = make_float4(acc[i][0], acc[i][1], acc[i][2], acc[i][3]);
        *(float4*)(Cp + (size_t)i * G4 + 4) = make_float4(acc[i][4], acc[i][5], acc[i][6], acc[i][7]);
    }
}

// ============================================================================
// Kernel 2: persistent LSTM recurrence. 128 blocks x 128 threads.
// Compute core identical to R4 (TB=2 batches x TJ=4 gates per thread).
// NEW: flag-array grid sync. Arrival = STG g_flag[bid]=t+1 (distinct addrs,
// no atomic serialization). Detection = warp 0 polls all 128 flags with one
// ld.volatile.v4 per lane + __all_sync, nanosleep backoff.
// ============================================================================
__global__ __launch_bounds__(TPB, 1)
void lstm_persist(const float* __restrict__ Whh,
                  const float* __restrict__ bih,
                  const float* __restrict__ bhh,
                  float* __restrict__ out)
{
    extern __shared__ float smem[];
    float* h_s = smem;                  // BB * HPAD
    float* w_s = smem + BB * HPAD;      // 16 * WPAD  (row r: gate r>>2, hidden r&3)

    const int tid  = threadIdx.x;
    const int bid  = blockIdx.x;
    const int lane = tid & 31;
    const int jl   = tid >> 5;          // warp id = local hidden index 0..3
    const int bp   = tid & 31;          // lane = batch-pair base
    const int b0   = bp;
    const int b1   = bp + 32;
    const int j    = bid * 4 + jl;      // global hidden index

    float* out_h = out;
    float* out_c = out + (size_t)SQ * BB * HD;

    // One-time: W_hh rows {g*512 + bid*4 + r} -> w_s[g*4+r][*], padded.
    for (int i = tid; i < 16 * (HD / 4); i += TPB) {
        int row = i >> 7, col = i & 127;
        int grow = (row >> 2) * HD + bid * 4 + (row & 3);
        *(float4*)(w_s + row * WPAD + (col << 2)) =
            *(const float4*)(Whh + (size_t)grow * HD + (col << 2));
    }
    // Biases for this thread's 4 gate columns.
    float bs0 = bih[0 * HD + j] + bhh[0 * HD + j];
    float bs1 = bih[1 * HD + j] + bhh[1 * HD + j];
    float bs2 = bih[2 * HD + j] + bhh[2 * HD + j];
    float bs3 = bih[3 * HD + j] + bhh[3 * HD + j];

    // h_0 = 0
    for (int i = tid; i < BB * HPAD; i += TPB) h_s[i] = 0.0f;
    __syncthreads();

    const ulonglong2* hr0 = (const ulonglong2*)(h_s + b0 * HPAD);
    const ulonglong2* hr1 = (const ulonglong2*)(h_s + b1 * HPAD);
    const ulonglong2* w0  = (const ulonglong2*)(w_s + (0 * 4 + jl) * WPAD);
    const ulonglong2* w1  = (const ulonglong2*)(w_s + (1 * 4 + jl) * WPAD);
    const ulonglong2* w2  = (const ulonglong2*)(w_s + (2 * 4 + jl) * WPAD);
    const ulonglong2* w3  = (const ulonglong2*)(w_s + (3 * 4 + jl) * WPAD);

    float c0 = 0.0f, c1 = 0.0f;         // register-resident cell states

    for (int t = 0; t < SQ; ++t) {
        // Prefetch x_proj (8 values): DRAM latency hides under the dot loop.
        const float* xq0 = g_xproj + ((size_t)t * BB + b0) * G4 + j;
        const float* xq1 = g_xproj + ((size_t)t * BB + b1) * G4 + j;
        float xa0 = __ldg(xq0);        float xb0 = __ldg(xq1);
        float xa1 = __ldg(xq0 + 512);  float xb1 = __ldg(xq1 + 512);
        float xa2 = __ldg(xq0 + 1024); float xb2 = __ldg(xq1 + 1024);
        float xa3 = __ldg(xq0 + 1536); float xb3 = __ldg(xq1 + 1536);

        // 8 dot products (2 batches x 4 gates), f32x2 packed along k.
        unsigned long long aA0 = 0, aA1 = 0, aA2 = 0, aA3 = 0;
        unsigned long long bA0 = 0, bA1 = 0, bA2 = 0, bA3 = 0;
        unsigned long long aB0 = 0, aB1 = 0, aB2 = 0, aB3 = 0;
        unsigned long long bB0 = 0, bB1 = 0, bB2 = 0, bB3 = 0;
#pragma unroll 8
        for (int k = 0; k < HD / 4; ++k) {
            ulonglong2 h0v = hr0[k];
            ulonglong2 h1v = hr1[k];
            ulonglong2 wv;
            wv = w0[k];
            fma2(aA0, h0v.x, wv.x); fma2(bA0, h0v.y, wv.y);
            fma2(aB0, h1v.x, wv.x); fma2(bB0, h1v.y, wv.y);
            wv = w1[k];
            fma2(aA1, h0v.x, wv.x); fma2(bA1, h0v.y, wv.y);
            fma2(aB1, h1v.x, wv.x); fma2(bB1, h1v.y, wv.y);
            wv = w2[k];
            fma2(aA2, h0v.x, wv.x); fma2(bA2, h0v.y, wv.y);
            fma2(aB2, h1v.x, wv.x); fma2(bB2, h1v.y, wv.y);
            wv = w3[k];
            fma2(aA3, h0v.x, wv.x); fma2(bA3, h0v.y, wv.y);
            fma2(aB3, h1v.x, wv.x); fma2(bB3, h1v.y, wv.y);
        }

        float vA0 = red2(aA0) + red2(bA0);
        float vA1 = red2(aA1) + red2(bA1);
        float vA2 = red2(aA2) + red2(bA2);
        float vA3 = red2(aA3) + red2(bA3);
        float vB0 = red2(aB0) + red2(bB0);
        float vB1 = red2(aB1) + red2(bB1);
        float vB2 = red2(aB2) + red2(bB2);
        float vB3 = red2(aB3) + red2(bB3);

        // Gates (torch order i, f, g, o) + local state update.
        float iA = sigf(vA0 + xa0 + bs0);
        float fA = sigf(vA1 + xa1 + bs1);
        float gA = tanhf(vA2 + xa2 + bs2);
        float oA = sigf(vA3 + xa3 + bs3);
        c0 = fA * c0 + iA * gA;
        float hA = oA * tanhf(c0);

        float iB = sigf(vB0 + xb0 + bs0);
        float fB = sigf(vB1 + xb1 + bs1);
        float gB = tanhf(vB2 + xb2 + bs2);
        float oB = sigf(vB3 + xb3 + bs3);
        c1 = fB * c1 + iB * gB;
        float hB = oB * tanhf(c1);

        size_t base = (size_t)t * BB * HD + j;
        out_h[base + (size_t)b0 * HD] = hA;
        out_h[base + (size_t)b1 * HD] = hB;
        out_c[base + (size_t)b0 * HD] = c0;
        out_c[base + (size_t)b1 * HD] = c1;

        // ---- signal: h_t (this block's slice) is globally visible ----
        __threadfence();                 // push this thread's h stores to gpu scope
        __syncthreads();                 // all threads' fences done
        if (tid == 0)
            *((volatile int*)&g_flag[bid]) = t + 1;

        if (t + 1 < SQ) {
            // ---- wait: all 128 blocks have published step t ----
            if (tid < 32) {
                const int want = t + 1;
                const int* fp = g_flag + (lane << 2);   // 4 flags per lane
                for (;;) {
                    int f0, f1, f2, f3;
                    asm volatile("ld.volatile.global.v4.b32 {%0,%1,%2,%3}, [%4];"
                                 : "=r"(f0), "=r"(f1), "=r"(f2), "=r"(f3)
                                 : "l"(fp));
                    bool ok = (f0 >= want) & (f1 >= want) & (f2 >= want) & (f3 >= want);
                    if (__all_sync(0xFFFFFFFFu, ok)) break;
                    asm volatile("nanosleep.u32 %0;" :: "r"(96));
                }
                __threadfence();         // order subsequent h loads after flag observation
            }
            __syncthreads();

            // ---- stage h_t into padded SMEM (coalesced LDG.128) ----
            const float4* hp = (const float4*)(out_h + (size_t)t * BB * HD);
#pragma unroll 4
            for (int i = tid; i < BB * (HD / 4); i += TPB) {
                int bb2 = i >> 7, u = i & 127;
                *(float4*)(h_s + bb2 * HPAD + (u << 2)) = hp[i];
            }
            __syncthreads();
        }
    }

    // End-of-launch: one legacy barrier, then reset flags for graph replay.
    gridbar(NBLK);
    if (tid == 0) g_flag[bid] = 0;
}

// ============================================================================
// Launch: inputs: x, W_ih, W_hh, b_ih, b_hh. Output: [h_out | c_out] fp32.
// ============================================================================
extern "C" void kernel_launch(void* const* d_in, const int* in_sizes, int n_in,
                              void* d_out, int out_size)
{
    (void)in_sizes; (void)n_in; (void)out_size;
    const float* x   = (const float*)d_in[0];
    const float* Wih = (const float*)d_in[1];
    const float* Whh = (const float*)d_in[2];
    const float* bih = (const float*)d_in[3];
    const float* bhh = (const float*)d_in[4];
    float* out = (float*)d_out;

    const int smem_bytes = (BB * HPAD + 16 * WPAD) * (int)sizeof(float);
    cudaFuncSetAttribute(lstm_persist, cudaFuncAttributeMaxDynamicSharedMemorySize, smem_bytes);

    dim3 g1(G4 / 128, (SQ * BB) / 128);   // (16, 1024)
    xproj_gemm<<<g1, 256>>>(x, Wih);
    lstm_persist<<<NBLK, TPB, smem_bytes>>>(Whh, bih, bhh, out);
}

// round 8
// speedup vs baseline: 1.4184x; 1.4184x over previous
#include <cuda_runtime.h>
#include <math.h>

#define SQ 2048   // sequence length
#define BB 64     // batch
#define DI 512    // input dim
#define HD 512    // hidden dim
#define G4 2048   // 4*HD

#define NBLK 128          // persistent blocks, 1/SM, co-resident
#define TPB 256           // threads per persistent block (8 warps -> 2/SMSP)
#define HPAD 516          // padded h row (floats): conflict-free LDS.128
#define WPAD 516

// ---- device scratch (allocation-free per the rules) ----
__device__ float g_xproj[2048ULL * 64ULL * 2048ULL];  // 1 GiB: x @ W_ih^T
__device__ unsigned long long g_bar;                  // grid barrier ticket counter

// ---- packed f32x2 helpers ----
__device__ __forceinline__ void fma2(unsigned long long& d,
                                     unsigned long long a, unsigned long long b) {
    asm("fma.rn.f32x2 %0, %1, %2, %0;" : "+l"(d) : "l"(a), "l"(b));
}
__device__ __forceinline__ float red2(unsigned long long v) {
    float lo, hi;
    asm("mov.b64 {%0, %1}, %2;" : "=f"(lo), "=f"(hi) : "l"(v));
    return lo + hi;
}

__device__ __forceinline__ float sigf(float x) { return 1.0f / (1.0f + __expf(-x)); }

// Grid-wide barrier: monotonic u64 ticket counter (survives graph replays;
// each launch adds a multiple of NBLK so generation math stays consistent).
// Proven cheap in R2/R4; flag-array alternative regressed (R7).
__device__ __forceinline__ void gridbar(unsigned nb) {
    __threadfence();
    __syncthreads();
    if (threadIdx.x == 0) {
        unsigned long long t = atomicAdd(&g_bar, 1ULL) + 1ULL;
        unsigned long long target = ((t + nb - 1ULL) / nb) * (unsigned long long)nb;
        while (*((volatile unsigned long long*)&g_bar) < target) { }
        __threadfence();
    }
    __syncthreads();
}

// ============================================================================
// Kernel 1: x_proj[m][n] = sum_k x[m][k] * W_ih[n][k]     (plain fp32 SGEMM)
// M=131072, N=2048, K=512. 128x128 tile, BK=8, 256 thr, 8x8 microtile.
// ============================================================================
__global__ __launch_bounds__(256, 2)
void xproj_gemm(const float* __restrict__ A, const float* __restrict__ W)
{
    __shared__ float As[8][128];
    __shared__ float Bs[8][128];

    const int bn  = blockIdx.x;
    const int bm  = blockIdx.y;
    const int tid = threadIdx.x;

    const int arow = tid >> 1;
    const int acol = (tid & 1) << 2;
    const float* Ag = A + (size_t)(bm * 128 + arow) * DI + acol;
    const float* Wg = W + (size_t)(bn * 128 + arow) * DI + acol;

    const int tx = tid & 15;
    const int ty = tid >> 4;

    float acc[8][8];
#pragma unroll
    for (int i = 0; i < 8; i++)
#pragma unroll
        for (int j = 0; j < 8; j++) acc[i][j] = 0.0f;

    for (int kt = 0; kt < DI; kt += 8) {
        float4 av = *(const float4*)(Ag + kt);
        float4 wv = *(const float4*)(Wg + kt);
        __syncthreads();
        As[acol + 0][arow] = av.x; As[acol + 1][arow] = av.y;
        As[acol + 2][arow] = av.z; As[acol + 3][arow] = av.w;
        Bs[acol + 0][arow] = wv.x; Bs[acol + 1][arow] = wv.y;
        Bs[acol + 2][arow] = wv.z; Bs[acol + 3][arow] = wv.w;
        __syncthreads();
#pragma unroll
        for (int k = 0; k < 8; k++) {
            float ar[8], br[8];
            *(float4*)(ar)     = *(const float4*)&As[k][ty * 8];
            *(float4*)(ar + 4) = *(const float4*)&As[k][ty * 8 + 4];
            *(float4*)(br)     = *(const float4*)&Bs[k][tx * 8];
            *(float4*)(br + 4) = *(const float4*)&Bs[k][tx * 8 + 4];
#pragma unroll
            for (int i = 0; i < 8; i++)
#pragma unroll
                for (int j = 0; j < 8; j++)
                    acc[i][j] += ar[i] * br[j];
        }
    }

    float* Cp = g_xproj + (size_t)(bm * 128 + ty * 8) * G4 + (size_t)(bn * 128 + tx * 8);
#pragma unroll
    for (int i = 0; i < 8; i++) {
        *(float4*)(Cp + (size_t)i * G4)     = make_float4(acc[i][0], acc[i][1], acc[i][2], acc[i][3]);
        *(float4*)(Cp + (size_t)i * G4 + 4) = make_float4(acc[i][4], acc[i][5], acc[i][6], acc[i][7]);
    }
}

// ============================================================================
// Kernel 2: persistent LSTM recurrence. 128 blocks x 256 threads (8 warps,
// 2 per SMSP for latency hiding — R4's 1/SMSP exposed every stall).
// Block owns hidden j in [bid*4, bid*4+4). Warp w: jl = w>>1, half = w&1.
// Thread = (batch b = half*32+lane, j): computes all 4 gates (TB1 x TJ4).
// Per k4-iter: 1 strided h LDS.128 + 4 broadcast w LDS.128 + 8 FFMA2.
// One ticket barrier per step; c register-resident for all 2048 steps.
// ============================================================================
__global__ __launch_bounds__(TPB, 1)
void lstm_persist(const float* __restrict__ Whh,
                  const float* __restrict__ bih,
                  const float* __restrict__ bhh,
                  float* __restrict__ out)
{
    extern __shared__ float smem[];
    float* h_s = smem;                  // BB * HPAD
    float* w_s = smem + BB * HPAD;      // 16 * WPAD  (row r: gate r>>2, hidden r&3)

    const int tid  = threadIdx.x;
    const int bid  = blockIdx.x;
    const int lane = tid & 31;
    const int wid  = tid >> 5;          // 0..7
    const int jl   = wid >> 1;          // local hidden index 0..3
    const int half = wid & 1;           // batch half
    const int b    = half * 32 + lane;  // batch 0..63
    const int j    = bid * 4 + jl;      // global hidden index

    float* out_h = out;
    float* out_c = out + (size_t)SQ * BB * HD;

    // One-time: W_hh rows {g*512 + bid*4 + r} -> w_s[g*4+r][*], padded.
    for (int i = tid; i < 16 * (HD / 4); i += TPB) {
        int row = i >> 7, col = i & 127;
        int grow = (row >> 2) * HD + bid * 4 + (row & 3);
        *(float4*)(w_s + row * WPAD + (col << 2)) =
            *(const float4*)(Whh + (size_t)grow * HD + (col << 2));
    }
    // Biases for this thread's 4 gate columns.
    float bs0 = bih[0 * HD + j] + bhh[0 * HD + j];
    float bs1 = bih[1 * HD + j] + bhh[1 * HD + j];
    float bs2 = bih[2 * HD + j] + bhh[2 * HD + j];
    float bs3 = bih[3 * HD + j] + bhh[3 * HD + j];

    // h_0 = 0
    for (int i = tid; i < BB * HPAD; i += TPB) h_s[i] = 0.0f;
    __syncthreads();

    const ulonglong2* hr = (const ulonglong2*)(h_s + b * HPAD);
    const ulonglong2* w0 = (const ulonglong2*)(w_s + (0 * 4 + jl) * WPAD);
    const ulonglong2* w1 = (const ulonglong2*)(w_s + (1 * 4 + jl) * WPAD);
    const ulonglong2* w2 = (const ulonglong2*)(w_s + (2 * 4 + jl) * WPAD);
    const ulonglong2* w3 = (const ulonglong2*)(w_s + (3 * 4 + jl) * WPAD);

    float c = 0.0f;                     // register-resident cell state

    for (int t = 0; t < SQ; ++t) {
        // Prefetch x_proj (4 values): DRAM latency hides under the dot loop.
        const float* xq = g_xproj + ((size_t)t * BB + b) * G4 + j;
        float xp0 = __ldg(xq);
        float xp1 = __ldg(xq + 512);
        float xp2 = __ldg(xq + 1024);
        float xp3 = __ldg(xq + 1536);

        // 4 dot products (gates i,f,g,o), f32x2 packed along k.
        unsigned long long a0 = 0, a1 = 0, a2 = 0, a3 = 0;  // even-k pair acc
        unsigned long long e0 = 0, e1 = 0, e2 = 0, e3 = 0;  // odd-k pair acc
#pragma unroll 8
        for (int k = 0; k < HD / 4; ++k) {
            ulonglong2 hv = hr[k];
            ulonglong2 wv;
            wv = w0[k]; fma2(a0, hv.x, wv.x); fma2(e0, hv.y, wv.y);
            wv = w1[k]; fma2(a1, hv.x, wv.x); fma2(e1, hv.y, wv.y);
            wv = w2[k]; fma2(a2, hv.x, wv.x); fma2(e2, hv.y, wv.y);
            wv = w3[k]; fma2(a3, hv.x, wv.x); fma2(e3, hv.y, wv.y);
        }
        float v0 = red2(a0) + red2(e0);
        float v1 = red2(a1) + red2(e1);
        float v2 = red2(a2) + red2(e2);
        float v3 = red2(a3) + red2(e3);

        // Gates (torch order i, f, g, o) + local state update.
        float ig = sigf(v0 + xp0 + bs0);
        float fg = sigf(v1 + xp1 + bs1);
        float gg = tanhf(v2 + xp2 + bs2);
        float og = sigf(v3 + xp3 + bs3);
        c = fg * c + ig * gg;
        float h = og * tanhf(c);

        size_t o = (size_t)t * BB * HD + (size_t)b * HD + j;
        out_h[o] = h;
        out_c[o] = c;

        if (t + 1 < SQ) {
            gridbar(NBLK);   // all h_t globally visible
            // Stage h_t into padded SMEM (coalesced LDG.128 from L2).
            const float4* hp = (const float4*)(out_h + (size_t)t * BB * HD);
#pragma unroll 4
            for (int i = tid; i < BB * (HD / 4); i += TPB) {
                int bb2 = i >> 7, u = i & 127;
                *(float4*)(h_s + bb2 * HPAD + (u << 2)) = hp[i];
            }
            __syncthreads();
        }
    }
}

// ============================================================================
// Launch: inputs: x, W_ih, W_hh, b_ih, b_hh. Output: [h_out | c_out] fp32.
// ============================================================================
extern "C" void kernel_launch(void* const* d_in, const int* in_sizes, int n_in,
                              void* d_out, int out_size)
{
    (void)in_sizes; (void)n_in; (void)out_size;
    const float* x   = (const float*)d_in[0];
    const float* Wih = (const float*)d_in[1];
    const float* Whh = (const float*)d_in[2];
    const float* bih = (const float*)d_in[3];
    const float* bhh = (const float*)d_in[4];
    float* out = (float*)d_out;

    const int smem_bytes = (BB * HPAD + 16 * WPAD) * (int)sizeof(float);
    cudaFuncSetAttribute(lstm_persist, cudaFuncAttributeMaxDynamicSharedMemorySize, smem_bytes);

    dim3 g1(G4 / 128, (SQ * BB) / 128);   // (16, 1024)
    xproj_gemm<<<g1, 256>>>(x, Wih);
    lstm_persist<<<NBLK, TPB, smem_bytes>>>(Whh, bih, bhh, out);
}